// round 5
// baseline (speedup 1.0000x reference)
#include <cuda_runtime.h>
#include <cstdint>

// out[n,d] = mean_f( x[n,f]*W[f,d] + b[f,d] ) = (x@W)[n,d]/256 + mean_f b[f,d]
// N=8192, K=256, D=64. bf16 3-term split on tensor cores (baseline PTX mma.sync).
//
// Two kernels in one graph:
//  prep: W -> Wf (bf16 hi/lo in mma-B-fragment layout), b -> mb_g
//  main: x-tile convert (smem) + ldmatrix A + LDG.128 B-frags + HMMA + epilogue

typedef uint32_t u32;

#define NROWS  8192
#define NF     256
#define ND     64
#define TILE_M 32
#define THREADS 256
#define NBLOCKS (NROWS / TILE_M)   // 256

#define XPITCHB (264 * 2)   // 528B padded row (conflict-free ldmatrix)
#define XH_OFF 0
#define XL_OFF (XH_OFF + TILE_M * XPITCHB)   // 16896
#define SMEM_BYTES (XL_OFF + TILE_M * XPITCHB)  // 33792

// Wf[ki][col][t] : uint4 {hi(k=2t,2t+1), hi(k=2t+8,2t+9), lo(..), lo(..)}
__device__ uint4 Wf_g[16 * 64 * 4];
__device__ float mb_g[64];

__device__ __forceinline__ u32 smem_u32(const void* p) {
    u32 a;
    asm("{ .reg .u64 t; cvta.to.shared.u64 t, %1; cvt.u32.u64 %0, t; }" : "=r"(a) : "l"(p));
    return a;
}
// hi = bf16x2{lo=bf16(a), hi=bf16(b)}; lo = residual pair
__device__ __forceinline__ void cvt_split(float a, float b, u32& hi, u32& lo) {
    asm("cvt.rn.bf16x2.f32 %0, %1, %2;" : "=r"(hi) : "f"(b), "f"(a));
    float ha = __uint_as_float(hi << 16);
    float hb = __uint_as_float(hi & 0xFFFF0000u);
    float ra = a - ha;
    float rb = b - hb;
    asm("cvt.rn.bf16x2.f32 %0, %1, %2;" : "=r"(lo) : "f"(rb), "f"(ra));
}
__device__ __forceinline__ void ldsm4(u32* r, u32 addr) {
    asm volatile("ldmatrix.sync.aligned.m8n8.x4.shared.b16 {%0,%1,%2,%3}, [%4];"
        : "=r"(r[0]), "=r"(r[1]), "=r"(r[2]), "=r"(r[3]) : "r"(addr));
}
__device__ __forceinline__ void mma16816(float* c, const u32* a, u32 b0, u32 b1) {
    asm volatile(
        "mma.sync.aligned.m16n8k16.row.col.f32.bf16.bf16.f32 "
        "{%0,%1,%2,%3}, {%4,%5,%6,%7}, {%8,%9}, {%0,%1,%2,%3};"
        : "+f"(c[0]), "+f"(c[1]), "+f"(c[2]), "+f"(c[3])
        : "r"(a[0]), "r"(a[1]), "r"(a[2]), "r"(a[3]), "r"(b0), "r"(b1));
}

// ---------------- prep kernel ----------------
__global__ void __launch_bounds__(256)
prep_kernel(const float* __restrict__ W, const float* __restrict__ b)
{
    const int tid = threadIdx.x;
    if (blockIdx.x < 16) {
        // one thread per (ki, col, t) entry
        int idx = blockIdx.x * 256 + tid;          // 0..4095
        int ki  = idx >> 8;
        int col = (idx >> 2) & 63;
        int t   = idx & 3;
        int k0  = ki * 16 + 2 * t;
        float w0 = W[(k0    ) * ND + col];
        float w1 = W[(k0 + 1) * ND + col];
        float w2 = W[(k0 + 8) * ND + col];
        float w3 = W[(k0 + 9) * ND + col];
        u32 h01, l01, h23, l23;
        cvt_split(w0, w1, h01, l01);
        cvt_split(w2, w3, h23, l23);
        Wf_g[idx] = make_uint4(h01, h23, l01, l23);
    } else {
        // mb[d] = mean_f b[f][d]
        __shared__ float4 sc[256];
        const int qd = tid & 15;
        const int fr = tid >> 4;
        const float4* b4 = (const float4*)b;   // [256][16] float4
        float4 s = make_float4(0.f, 0.f, 0.f, 0.f);
        #pragma unroll
        for (int k = 0; k < 16; ++k) {
            float4 v = b4[(fr * 16 + k) * 16 + qd];
            s.x += v.x; s.y += v.y; s.z += v.z; s.w += v.w;
        }
        sc[tid] = s;
        __syncthreads();
        if (tid < 16) {
            float4 m = make_float4(0.f, 0.f, 0.f, 0.f);
            #pragma unroll
            for (int g = 0; g < 16; ++g) {
                float4 v = sc[tid + 16 * g];
                m.x += v.x; m.y += v.y; m.z += v.z; m.w += v.w;
            }
            const float inv = 1.f / 256.f;
            m.x *= inv; m.y *= inv; m.z *= inv; m.w *= inv;
            ((float4*)mb_g)[tid] = m;
        }
    }
}

// ---------------- main kernel ----------------
__global__ void __launch_bounds__(THREADS, 3)
nanembed_hmma_kernel(const float* __restrict__ x, float* __restrict__ out)
{
    extern __shared__ char smem[];
    const u32 sb = smem_u32(smem);
    const int tid = threadIdx.x;

    // ---- convert x tile (32 x 256 f32) -> XH/XL bf16 padded ----
    {
        const float4* x4 = (const float4*)(x + (size_t)blockIdx.x * TILE_M * NF);
        #pragma unroll
        for (int i = 0; i < 8; ++i) {
            int idx = tid + THREADS * i;        // 0..2047
            int row = idx >> 6;
            int c4  = idx & 63;
            float4 v = x4[idx];
            u32 h0, l0, h1, l1;
            cvt_split(v.x, v.y, h0, l0);
            cvt_split(v.z, v.w, h1, l1);
            u32 off = (u32)(row * XPITCHB + c4 * 8);
            asm volatile("st.shared.v2.b32 [%0], {%1, %2};"
                         :: "r"(sb + XH_OFF + off), "r"(h0), "r"(h1) : "memory");
            asm volatile("st.shared.v2.b32 [%0], {%1, %2};"
                         :: "r"(sb + XL_OFF + off), "r"(l0), "r"(l1) : "memory");
        }
    }
    __syncthreads();

    // ---- mainloop: warp = 16 rows x 16 cols ----
    const int wid  = tid >> 5;
    const int lane = tid & 31;
    const int r0   = (wid & 1) * 16;
    const int n0   = (wid >> 1) * 16;
    const int g    = lane >> 2;
    const int t    = lane & 3;

    const u32 aRow = (u32)(r0 + (lane & 15));
    const u32 aCol = (u32)((lane >> 4) * 16);
    u32 aAddrH = sb + XH_OFF + aRow * XPITCHB + aCol;
    u32 aAddrL = aAddrH + (u32)(XL_OFF - XH_OFF);

    // B frags: Wf_g[(ki*64 + col)*4 + t]; tile0 col=n0+g, tile1 col=n0+8+g
    const uint4* bp0 = Wf_g + ((n0 + g) * 4 + t);
    const uint4* bp1 = bp0 + 32;            // +8 cols * 4

    float acc0[4] = {0.f, 0.f, 0.f, 0.f};
    float acc1[4] = {0.f, 0.f, 0.f, 0.f};

    #pragma unroll 4
    for (int ki = 0; ki < 16; ++ki) {
        u32 ah[4], al[4];
        ldsm4(ah, aAddrH + (u32)ki * 32);
        ldsm4(al, aAddrL + (u32)ki * 32);
        uint4 b0 = bp0[ki * 256];           // 256 uint4 per ki step
        uint4 b1 = bp1[ki * 256];
        // n-tile 0
        mma16816(acc0, ah, b0.x, b0.y);     // hi*hi
        mma16816(acc0, ah, b0.z, b0.w);     // hi*lo
        mma16816(acc0, al, b0.x, b0.y);     // lo*hi
        // n-tile 1
        mma16816(acc1, ah, b1.x, b1.y);
        mma16816(acc1, ah, b1.z, b1.w);
        mma16816(acc1, al, b1.x, b1.y);
    }

    // ---- epilogue ----
    const float inv = 1.f / 256.f;
    const int grow = blockIdx.x * TILE_M + r0 + g;
    {
        int col = n0 + 2 * t;
        float2 m = *(const float2*)(mb_g + col);
        float2 o0, o1;
        o0.x = fmaf(acc0[0], inv, m.x); o0.y = fmaf(acc0[1], inv, m.y);
        o1.x = fmaf(acc0[2], inv, m.x); o1.y = fmaf(acc0[3], inv, m.y);
        *(float2*)(out + (size_t)grow * ND + col) = o0;
        *(float2*)(out + (size_t)(grow + 8) * ND + col) = o1;
    }
    {
        int col = n0 + 8 + 2 * t;
        float2 m = *(const float2*)(mb_g + col);
        float2 o0, o1;
        o0.x = fmaf(acc1[0], inv, m.x); o0.y = fmaf(acc1[1], inv, m.y);
        o1.x = fmaf(acc1[2], inv, m.x); o1.y = fmaf(acc1[3], inv, m.y);
        *(float2*)(out + (size_t)grow * ND + col) = o0;
        *(float2*)(out + (size_t)(grow + 8) * ND + col) = o1;
    }
}

extern "C" void kernel_launch(void* const* d_in, const int* in_sizes, int n_in,
                              void* d_out, int out_size)
{
    const float* x = (const float*)d_in[0];
    const float* W = (const float*)d_in[1];
    const float* b = (const float*)d_in[2];
    float* out = (float*)d_out;

    prep_kernel<<<17, 256>>>(W, b);
    cudaFuncSetAttribute(nanembed_hmma_kernel,
                         cudaFuncAttributeMaxDynamicSharedMemorySize, SMEM_BYTES);
    nanembed_hmma_kernel<<<NBLOCKS, THREADS, SMEM_BYTES>>>(x, out);
}